// round 4
// baseline (speedup 1.0000x reference)
#include <cuda_runtime.h>
#include <math.h>
#include <stdint.h>

// B=2, H=16, S=2048, DK=64
// Inputs: Q[B,H,S,DK] f32, K[B,H,S,DK] f32, V[B,H,S,DK] f32, mask[B,1,S,S] i32
// Output: concat( O[B,H,S,DK] f32, W[B,H,S,S] f32 )

#define BATCH 2
#define HEADS 16
#define SEQ   2048
#define DKDIM 64

// per-row partial softmax sums: [bh][q][ktile*2 + wk], 32 partials per row
__device__ float g_partial[(size_t)BATCH * HEADS * SEQ * 32];

// ---------------------------------------------------------------------------
__device__ __forceinline__ float f2tf32(float x) {
    uint32_t u;
    asm("cvt.rna.tf32.f32 %0, %1;" : "=r"(u) : "f"(x));
    return __uint_as_float(u);
}

__device__ __forceinline__ void mma_tf32(float c[4],
                                         uint32_t a0, uint32_t a1, uint32_t a2, uint32_t a3,
                                         uint32_t b0, uint32_t b1) {
    asm volatile(
        "mma.sync.aligned.m16n8k8.row.col.f32.tf32.tf32.f32 "
        "{%0,%1,%2,%3}, {%4,%5,%6,%7}, {%8,%9}, {%0,%1,%2,%3};\n"
        : "+f"(c[0]), "+f"(c[1]), "+f"(c[2]), "+f"(c[3])
        : "r"(a0), "r"(a1), "r"(a2), "r"(a3), "r"(b0), "r"(b1));
}

// ---------------------------------------------------------------------------
// Pass 1: W = mask ? exp(scale * Q K^T) : 0   (unnormalized), plus per-row
// partial sums to g_partial. 128q x 128k tile / block, 8 warps 4(q) x 2(k).
// ---------------------------------------------------------------------------
#define SQ_STRIDE 68

__global__ __launch_bounds__(256)
void sdpa_scores_kernel(const float* __restrict__ Q,
                        const float* __restrict__ K,
                        const int*   __restrict__ mask,
                        float* __restrict__ W)
{
    extern __shared__ float smem[];
    float* Qs = smem;                      // [128][SQ_STRIDE]
    float* Ks = smem + 128 * SQ_STRIDE;    // [128][SQ_STRIDE]

    const int bh   = blockIdx.z;
    const int b    = bh >> 4;              // H = 16
    const int q0   = blockIdx.y * 128;
    const int k0   = blockIdx.x * 128;
    const int tid  = threadIdx.x;
    const int lane = tid & 31;
    const int warp = tid >> 5;
    const int wq   = warp >> 1;            // 0..3
    const int wk   = warp & 1;             // 0..1

    const float* Qp = Q + ((size_t)bh * SEQ + q0) * DKDIM;
    const float* Kp = K + ((size_t)bh * SEQ + k0) * DKDIM;

    #pragma unroll
    for (int it = 0; it < 8; it++) {
        const int i = tid + it * 256;
        const int g = i & 15;
        const int r = i >> 4;
        float4 q4 = *(const float4*)(Qp + r * DKDIM + 4 * g);
        float4 k4 = *(const float4*)(Kp + r * DKDIM + 4 * g);
        float* qd = Qs + r * SQ_STRIDE + 4 * g;
        qd[0] = f2tf32(q4.x); qd[1] = f2tf32(q4.y);
        qd[2] = f2tf32(q4.z); qd[3] = f2tf32(q4.w);
        float* kd = Ks + r * SQ_STRIDE + 4 * g;
        kd[0] = f2tf32(k4.x); kd[1] = f2tf32(k4.y);
        kd[2] = f2tf32(k4.z); kd[3] = f2tf32(k4.w);
    }
    __syncthreads();

    float acc[2][8][4];
    #pragma unroll
    for (int i = 0; i < 2; i++)
        #pragma unroll
        for (int j = 0; j < 8; j++)
            #pragma unroll
            for (int t = 0; t < 4; t++) acc[i][j][t] = 0.f;

    const int qb  = wq * 32 + (lane >> 2);
    const int kb  = wk * 64 + (lane >> 2);
    const int dco = lane & 3;

    #pragma unroll
    for (int d0 = 0; d0 < DKDIM; d0 += 8) {
        uint32_t a[2][4];
        #pragma unroll
        for (int i = 0; i < 2; i++) {
            const float* base = Qs + (qb + i * 16) * SQ_STRIDE + d0 + dco;
            a[i][0] = __float_as_uint(base[0]);
            a[i][1] = __float_as_uint(base[8 * SQ_STRIDE]);
            a[i][2] = __float_as_uint(base[4]);
            a[i][3] = __float_as_uint(base[8 * SQ_STRIDE + 4]);
        }
        uint32_t bf[8][2];
        #pragma unroll
        for (int j = 0; j < 8; j++) {
            const float* base = Ks + (kb + j * 8) * SQ_STRIDE + d0 + dco;
            bf[j][0] = __float_as_uint(base[0]);
            bf[j][1] = __float_as_uint(base[4]);
        }
        #pragma unroll
        for (int i = 0; i < 2; i++)
            #pragma unroll
            for (int j = 0; j < 8; j++)
                mma_tf32(acc[i][j], a[i][0], a[i][1], a[i][2], a[i][3], bf[j][0], bf[j][1]);
    }

    // epilogue: scale, mask, exp, write; per-row partial sum -> g_partial
    const float scale = 0.125f;
    const int qrow0 = q0 + wq * 32 + (lane >> 2);
    const int kcol0 = k0 + wk * 64 + 2 * (lane & 3);
    #pragma unroll
    for (int i = 0; i < 2; i++) {
        #pragma unroll
        for (int rr = 0; rr < 2; rr++) {
            const int q = qrow0 + i * 16 + rr * 8;
            const int* mrow = mask + ((size_t)b * SEQ + q) * SEQ;
            float*    wrow = W    + ((size_t)bh * SEQ + q) * SEQ;
            float rsum = 0.f;
            #pragma unroll
            for (int j = 0; j < 8; j++) {
                const int kc = kcol0 + j * 8;
                int2 m = *(const int2*)(mrow + kc);
                float e0 = m.x ? __expf(acc[i][j][rr * 2 + 0] * scale) : 0.f;
                float e1 = m.y ? __expf(acc[i][j][rr * 2 + 1] * scale) : 0.f;
                *(float2*)(wrow + kc) = make_float2(e0, e1);
                rsum += e0 + e1;
            }
            rsum += __shfl_xor_sync(0xffffffffu, rsum, 1);
            rsum += __shfl_xor_sync(0xffffffffu, rsum, 2);
            if ((lane & 3) == 0)
                g_partial[((size_t)bh * SEQ + q) * 32 + blockIdx.x * 2 + wk] = rsum;
        }
    }
}

// ---------------------------------------------------------------------------
// Pass 2 (fused): normalize W in place AND compute O = W_norm @ V.
// Block: 128q x 64d, 256 threads = 8 warps 4(q) x 2(d), warp tile 32x32.
// ---------------------------------------------------------------------------
#define WS_STRIDE 68
#define VS_STRIDE 72

__global__ __launch_bounds__(256)
void sdpa_norm_out_kernel(float* __restrict__ W,
                          const float* __restrict__ V,
                          float* __restrict__ O)
{
    extern __shared__ float smem2[];
    float* Ws   = smem2;                            // [128][WS_STRIDE]
    float* Vs   = smem2 + 128 * WS_STRIDE;          // [64][VS_STRIDE]
    float* invs = Vs + 64 * VS_STRIDE;              // [128]

    const int bh   = blockIdx.y;
    const int q0   = blockIdx.x * 128;
    const int tid  = threadIdx.x;
    const int lane = tid & 31;
    const int warp = tid >> 5;
    const int wq   = warp >> 1;   // 0..3  (32-row q slice)
    const int wn   = warp & 1;    // 0..1  (32-col d slice)

    // row inverse sums from partials
    if (tid < 128) {
        const float4* pp = (const float4*)(g_partial + ((size_t)bh * SEQ + q0 + tid) * 32);
        float s = 0.f;
        #pragma unroll
        for (int i = 0; i < 8; i++) {
            float4 v = pp[i];
            s += (v.x + v.y) + (v.z + v.w);
        }
        invs[tid] = 1.0f / s;
    }
    __syncthreads();

    float* Wp = W + ((size_t)bh * SEQ + q0) * SEQ;
    const float* Vp = V + (size_t)bh * SEQ * DKDIM;

    float acc[2][4][4];
    #pragma unroll
    for (int i = 0; i < 2; i++)
        #pragma unroll
        for (int j = 0; j < 4; j++)
            #pragma unroll
            for (int t = 0; t < 4; t++) acc[i][j][t] = 0.f;

    for (int kc = 0; kc < SEQ; kc += 64) {
        // W tile: 128 rows x 16 float4 groups; normalize, write back, stage tf32
        #pragma unroll
        for (int it = 0; it < 8; it++) {
            const int i = tid + it * 256;
            const int g = i & 15;
            const int r = i >> 4;
            float* gp = Wp + (size_t)r * SEQ + kc + 4 * g;
            float4 w4 = *(const float4*)gp;
            const float inv = invs[r];
            w4.x *= inv; w4.y *= inv; w4.z *= inv; w4.w *= inv;
            *(float4*)gp = w4;
            float* wd = Ws + r * WS_STRIDE + 4 * g;
            wd[0] = f2tf32(w4.x); wd[1] = f2tf32(w4.y);
            wd[2] = f2tf32(w4.z); wd[3] = f2tf32(w4.w);
        }
        // V tile: 64 rows x 16 groups
        #pragma unroll
        for (int it = 0; it < 4; it++) {
            const int i = tid + it * 256;
            const int g = i & 15;
            const int r = i >> 4;
            float4 v4 = *(const float4*)(Vp + (size_t)(kc + r) * DKDIM + 4 * g);
            float* vd = Vs + r * VS_STRIDE + 4 * g;
            vd[0] = f2tf32(v4.x); vd[1] = f2tf32(v4.y);
            vd[2] = f2tf32(v4.z); vd[3] = f2tf32(v4.w);
        }
        __syncthreads();

        #pragma unroll
        for (int k8 = 0; k8 < 64; k8 += 8) {
            uint32_t a[2][4];
            #pragma unroll
            for (int i = 0; i < 2; i++) {
                const float* base = Ws + (wq * 32 + i * 16 + (lane >> 2)) * WS_STRIDE + k8 + (lane & 3);
                a[i][0] = __float_as_uint(base[0]);
                a[i][1] = __float_as_uint(base[8 * WS_STRIDE]);
                a[i][2] = __float_as_uint(base[4]);
                a[i][3] = __float_as_uint(base[8 * WS_STRIDE + 4]);
            }
            uint32_t bf[4][2];
            #pragma unroll
            for (int j = 0; j < 4; j++) {
                const float* base = Vs + (k8 + (lane & 3)) * VS_STRIDE + wn * 32 + j * 8 + (lane >> 2);
                bf[j][0] = __float_as_uint(base[0]);
                bf[j][1] = __float_as_uint(base[4 * VS_STRIDE]);
            }
            #pragma unroll
            for (int i = 0; i < 2; i++)
                #pragma unroll
                for (int j = 0; j < 4; j++)
                    mma_tf32(acc[i][j], a[i][0], a[i][1], a[i][2], a[i][3], bf[j][0], bf[j][1]);
        }
        __syncthreads();
    }

    // epilogue: O tile write
    #pragma unroll
    for (int i = 0; i < 2; i++) {
        #pragma unroll
        for (int rr = 0; rr < 2; rr++) {
            const int q = q0 + wq * 32 + i * 16 + rr * 8 + (lane >> 2);
            float* orow = O + ((size_t)bh * SEQ + q) * DKDIM + wn * 32;
            #pragma unroll
            for (int j = 0; j < 4; j++) {
                float2 v;
                v.x = acc[i][j][rr * 2 + 0];
                v.y = acc[i][j][rr * 2 + 1];
                *(float2*)(orow + j * 8 + 2 * (lane & 3)) = v;
            }
        }
    }
}

// ---------------------------------------------------------------------------
extern "C" void kernel_launch(void* const* d_in, const int* in_sizes, int n_in,
                              void* d_out, int out_size)
{
    const float* Q    = (const float*)d_in[0];
    const float* K    = (const float*)d_in[1];
    const float* V    = (const float*)d_in[2];
    const int*   mask = (const int*)  d_in[3];

    float* O = (float*)d_out;                                        // [B,H,S,DK]
    float* W = (float*)d_out + (size_t)BATCH * HEADS * SEQ * DKDIM;  // [B,H,S,S]

    const int scores_smem = 2 * 128 * SQ_STRIDE * sizeof(float);     // 69632 B
    cudaFuncSetAttribute(sdpa_scores_kernel,
                         cudaFuncAttributeMaxDynamicSharedMemorySize, scores_smem);
    const int fused_smem = (128 * WS_STRIDE + 64 * VS_STRIDE + 128) * sizeof(float); // 53760 B
    cudaFuncSetAttribute(sdpa_norm_out_kernel,
                         cudaFuncAttributeMaxDynamicSharedMemorySize, fused_smem);

    {
        dim3 grid(SEQ / 128, SEQ / 128, BATCH * HEADS);
        sdpa_scores_kernel<<<grid, 256, scores_smem>>>(Q, K, mask, W);
    }
    {
        dim3 grid(SEQ / 128, BATCH * HEADS);
        sdpa_norm_out_kernel<<<grid, 256, fused_smem>>>(W, V, O);
    }
}

// round 5
// speedup vs baseline: 1.1364x; 1.1364x over previous
#include <cuda_runtime.h>
#include <math.h>
#include <stdint.h>

// B=2, H=16, S=2048, DK=64
// Inputs: Q[B,H,S,DK] f32, K[B,H,S,DK] f32, V[B,H,S,DK] f32, mask[B,1,S,S] i32
// Output: concat( O[B,H,S,DK] f32, W[B,H,S,S] f32 )

#define BATCH 2
#define HEADS 16
#define SEQ   2048
#define DKDIM 64

__device__ float g_inv[(size_t)BATCH * HEADS * SEQ];

// ---------------------------------------------------------------------------
__device__ __forceinline__ float f2tf32(float x) {
    uint32_t u;
    asm("cvt.rna.tf32.f32 %0, %1;" : "=r"(u) : "f"(x));
    return __uint_as_float(u);
}

__device__ __forceinline__ void mma_tf32(float c[4],
                                         uint32_t a0, uint32_t a1, uint32_t a2, uint32_t a3,
                                         uint32_t b0, uint32_t b1) {
    asm volatile(
        "mma.sync.aligned.m16n8k8.row.col.f32.tf32.tf32.f32 "
        "{%0,%1,%2,%3}, {%4,%5,%6,%7}, {%8,%9}, {%0,%1,%2,%3};\n"
        : "+f"(c[0]), "+f"(c[1]), "+f"(c[2]), "+f"(c[3])
        : "r"(a0), "r"(a1), "r"(a2), "r"(a3), "r"(b0), "r"(b1));
}

#define QS_STRIDE 68
#define KS_STRIDE 68
#define VS_STRIDE 72
#define SS_STRIDE 68

// ---------------------------------------------------------------------------
// Fused kernel: per (bh, 128-row q tile):
//   loop k-tiles (64): S = QK^T (mma), e = mask ? exp(S/8) : 0,
//   STG e -> W (unnormalized), STS e -> smem, accO += e @ V (mma).
// End: rowsum -> inv, scale accO, store O; store inv to g_inv.
// 8 warps: mma1 4(q) x 2(k) -> 32x32 warp tiles; mma2 4(q) x 2(n) -> 32x32.
// ---------------------------------------------------------------------------
__global__ __launch_bounds__(256, 2)
void sdpa_fused_kernel(const float* __restrict__ Q,
                       const float* __restrict__ K,
                       const float* __restrict__ V,
                       const int*   __restrict__ mask,
                       float* __restrict__ W,
                       float* __restrict__ O)
{
    extern __shared__ float sm[];
    float* Qs   = sm;                         // [128][68]
    float* Ks   = Qs + 128 * QS_STRIDE;       // [64][68]
    float* Vs   = Ks + 64 * KS_STRIDE;        // [64][72]
    float* Ss   = Vs + 64 * VS_STRIDE;        // [128][68]
    float* rs   = Ss + 128 * SS_STRIDE;       // [128][2]
    float* invs = rs + 256;                   // [128]

    const int bh   = blockIdx.y;
    const int b    = bh >> 4;
    const int q0   = blockIdx.x * 128;
    const int tid  = threadIdx.x;
    const int lane = tid & 31;
    const int warp = tid >> 5;
    const int wq   = warp >> 1;   // 0..3
    const int wk   = warp & 1;    // 0..1  (k-half for mma1, n-half for mma2)

    const float* Qp = Q + ((size_t)bh * SEQ + q0) * DKDIM;
    const float* Kp = K + (size_t)bh * SEQ * DKDIM;
    const float* Vp = V + (size_t)bh * SEQ * DKDIM;

    // ---- load Q tile (persistent) ----
    #pragma unroll
    for (int it = 0; it < 8; it++) {
        const int i = tid + it * 256;
        const int g = i & 15;
        const int r = i >> 4;
        float4 q4 = *(const float4*)(Qp + r * DKDIM + 4 * g);
        float* qd = Qs + r * QS_STRIDE + 4 * g;
        qd[0] = f2tf32(q4.x); qd[1] = f2tf32(q4.y);
        qd[2] = f2tf32(q4.z); qd[3] = f2tf32(q4.w);
    }

    // K/V tile staging: each thread 2 float4 from K, 2 from V per half-step
    // (64 rows x 16 groups = 1024 tasks; 256 thr -> 4 each)
    const int lg = tid & 15;          // col group
    const int lr = tid >> 4;          // row base (0..15), rows lr + 16*it
    float4 kreg[4], vreg[4];

    // preload tile 0
    #pragma unroll
    for (int it = 0; it < 4; it++) {
        const int r = lr + 16 * it;
        kreg[it] = *(const float4*)(Kp + (size_t)r * DKDIM + 4 * lg);
        vreg[it] = *(const float4*)(Vp + (size_t)r * DKDIM + 4 * lg);
    }

    float accO[2][4][4];
    #pragma unroll
    for (int i = 0; i < 2; i++)
        #pragma unroll
        for (int j = 0; j < 4; j++)
            #pragma unroll
            for (int t = 0; t < 4; t++) accO[i][j][t] = 0.f;
    float rsum[2][2] = {{0.f, 0.f}, {0.f, 0.f}};

    const float scale = 0.125f;
    const int qrow_l = wq * 32 + (lane >> 2);   // local q row base
    const int kcol_l = wk * 32 + 2 * (lane & 3);

    __syncthreads();   // Qs ready

    for (int kt = 0; kt < 32; kt++) {
        // stage K/V tile from regs
        #pragma unroll
        for (int it = 0; it < 4; it++) {
            const int r = lr + 16 * it;
            float* kd = Ks + r * KS_STRIDE + 4 * lg;
            kd[0] = f2tf32(kreg[it].x); kd[1] = f2tf32(kreg[it].y);
            kd[2] = f2tf32(kreg[it].z); kd[3] = f2tf32(kreg[it].w);
            float* vd = Vs + r * VS_STRIDE + 4 * lg;
            vd[0] = f2tf32(vreg[it].x); vd[1] = f2tf32(vreg[it].y);
            vd[2] = f2tf32(vreg[it].z); vd[3] = f2tf32(vreg[it].w);
        }
        __syncthreads();

        // prefetch next tile (overlaps with both mma phases)
        if (kt + 1 < 32) {
            const float* Kn = Kp + (size_t)(kt + 1) * 64 * DKDIM;
            const float* Vn = Vp + (size_t)(kt + 1) * 64 * DKDIM;
            #pragma unroll
            for (int it = 0; it < 4; it++) {
                const int r = lr + 16 * it;
                kreg[it] = *(const float4*)(Kn + (size_t)r * DKDIM + 4 * lg);
                vreg[it] = *(const float4*)(Vn + (size_t)r * DKDIM + 4 * lg);
            }
        }

        // ---- mma1: S = Q @ K^T  (warp: 32q x 32k) ----
        float accS[2][4][4];
        #pragma unroll
        for (int i = 0; i < 2; i++)
            #pragma unroll
            for (int j = 0; j < 4; j++)
                #pragma unroll
                for (int t = 0; t < 4; t++) accS[i][j][t] = 0.f;

        #pragma unroll
        for (int d0 = 0; d0 < DKDIM; d0 += 8) {
            uint32_t a[2][4];
            #pragma unroll
            for (int i = 0; i < 2; i++) {
                const float* base = Qs + (qrow_l + i * 16) * QS_STRIDE + d0 + (lane & 3);
                a[i][0] = __float_as_uint(base[0]);
                a[i][1] = __float_as_uint(base[8 * QS_STRIDE]);
                a[i][2] = __float_as_uint(base[4]);
                a[i][3] = __float_as_uint(base[8 * QS_STRIDE + 4]);
            }
            uint32_t bf[4][2];
            #pragma unroll
            for (int j = 0; j < 4; j++) {
                const float* base = Ks + (wk * 32 + j * 8 + (lane >> 2)) * KS_STRIDE + d0 + (lane & 3);
                bf[j][0] = __float_as_uint(base[0]);
                bf[j][1] = __float_as_uint(base[4]);
            }
            #pragma unroll
            for (int i = 0; i < 2; i++)
                #pragma unroll
                for (int j = 0; j < 4; j++)
                    mma_tf32(accS[i][j], a[i][0], a[i][1], a[i][2], a[i][3], bf[j][0], bf[j][1]);
        }

        // ---- epilogue: exp + mask, STG W, STS Ss, rowsum ----
        #pragma unroll
        for (int i = 0; i < 2; i++) {
            #pragma unroll
            for (int rr = 0; rr < 2; rr++) {
                const int rl = qrow_l + i * 16 + rr * 8;
                const int q  = q0 + rl;
                const int kbase = kt * 64;
                const int* mrow = mask + ((size_t)b * SEQ + q) * SEQ + kbase;
                float*    wrow = W    + ((size_t)bh * SEQ + q) * SEQ + kbase;
                float* ssrow = Ss + rl * SS_STRIDE;
                #pragma unroll
                for (int j = 0; j < 4; j++) {
                    const int c = kcol_l + j * 8;
                    int2 m = *(const int2*)(mrow + c);
                    float e0 = m.x ? __expf(accS[i][j][rr * 2 + 0] * scale) : 0.f;
                    float e1 = m.y ? __expf(accS[i][j][rr * 2 + 1] * scale) : 0.f;
                    *(float2*)(wrow + c) = make_float2(e0, e1);
                    *(float2*)(ssrow + c) = make_float2(f2tf32(e0), f2tf32(e1));
                    rsum[i][rr] += e0 + e1;
                }
            }
        }
        __syncthreads();

        // ---- mma2: accO += Ss @ Vs  (warp: 32q x 32n) ----
        #pragma unroll
        for (int k8 = 0; k8 < 64; k8 += 8) {
            uint32_t a[2][4];
            #pragma unroll
            for (int i = 0; i < 2; i++) {
                const float* base = Ss + (qrow_l + i * 16) * SS_STRIDE + k8 + (lane & 3);
                a[i][0] = __float_as_uint(base[0]);
                a[i][1] = __float_as_uint(base[8 * SS_STRIDE]);
                a[i][2] = __float_as_uint(base[4]);
                a[i][3] = __float_as_uint(base[8 * SS_STRIDE + 4]);
            }
            uint32_t bf[4][2];
            #pragma unroll
            for (int j = 0; j < 4; j++) {
                const float* base = Vs + (k8 + (lane & 3)) * VS_STRIDE + wk * 32 + j * 8 + (lane >> 2);
                bf[j][0] = __float_as_uint(base[0]);
                bf[j][1] = __float_as_uint(base[4 * VS_STRIDE]);
            }
            #pragma unroll
            for (int i = 0; i < 2; i++)
                #pragma unroll
                for (int j = 0; j < 4; j++)
                    mma_tf32(accO[i][j], a[i][0], a[i][1], a[i][2], a[i][3], bf[j][0], bf[j][1]);
        }
        __syncthreads();
    }

    // ---- rowsum reduction -> inv ----
    #pragma unroll
    for (int i = 0; i < 2; i++)
        #pragma unroll
        for (int rr = 0; rr < 2; rr++) {
            float r = rsum[i][rr];
            r += __shfl_xor_sync(0xffffffffu, r, 1);
            r += __shfl_xor_sync(0xffffffffu, r, 2);
            if ((lane & 3) == 0)
                rs[(qrow_l + i * 16 + rr * 8) * 2 + wk] = r;
        }
    __syncthreads();
    if (tid < 128) {
        const float iv = 1.0f / (rs[2 * tid] + rs[2 * tid + 1]);
        invs[tid] = iv;
        g_inv[(size_t)bh * SEQ + q0 + tid] = iv;
    }
    __syncthreads();

    // ---- scale accO by row inverse, store O ----
    #pragma unroll
    for (int i = 0; i < 2; i++) {
        #pragma unroll
        for (int rr = 0; rr < 2; rr++) {
            const int rl = qrow_l + i * 16 + rr * 8;
            const float iv = invs[rl];
            float* orow = O + ((size_t)bh * SEQ + q0 + rl) * DKDIM + wk * 32;
            #pragma unroll
            for (int j = 0; j < 4; j++) {
                float2 v;
                v.x = accO[i][j][rr * 2 + 0] * iv;
                v.y = accO[i][j][rr * 2 + 1] * iv;
                *(float2*)(orow + j * 8 + 2 * (lane & 3)) = v;
            }
        }
    }
}

// ---------------------------------------------------------------------------
// Normalize W in place: one block per row, pure streaming.
// ---------------------------------------------------------------------------
__global__ __launch_bounds__(256)
void sdpa_normw_kernel(float* __restrict__ Wm)
{
    const size_t row = blockIdx.x;
    const float inv = g_inv[row];
    float4* p = (float4*)(Wm + row * SEQ);
    const int t = threadIdx.x;
    float4 a = p[t];
    float4 c = p[t + 256];
    a.x *= inv; a.y *= inv; a.z *= inv; a.w *= inv;
    c.x *= inv; c.y *= inv; c.z *= inv; c.w *= inv;
    p[t]       = a;
    p[t + 256] = c;
}

// ---------------------------------------------------------------------------
extern "C" void kernel_launch(void* const* d_in, const int* in_sizes, int n_in,
                              void* d_out, int out_size)
{
    const float* Q    = (const float*)d_in[0];
    const float* K    = (const float*)d_in[1];
    const float* V    = (const float*)d_in[2];
    const int*   mask = (const int*)  d_in[3];

    float* O = (float*)d_out;                                        // [B,H,S,DK]
    float* W = (float*)d_out + (size_t)BATCH * HEADS * SEQ * DKDIM;  // [B,H,S,S]

    const int fused_smem =
        (128 * QS_STRIDE + 64 * KS_STRIDE + 64 * VS_STRIDE + 128 * SS_STRIDE + 256 + 128)
        * (int)sizeof(float);   // 107,008 B
    cudaFuncSetAttribute(sdpa_fused_kernel,
                         cudaFuncAttributeMaxDynamicSharedMemorySize, fused_smem);

    {
        dim3 grid(SEQ / 128, BATCH * HEADS);
        sdpa_fused_kernel<<<grid, 256, fused_smem>>>(Q, K, V, mask, W, O);
    }
    {
        dim3 grid(BATCH * HEADS * SEQ);
        sdpa_normw_kernel<<<grid, 256>>>(W);
    }
}